// round 14
// baseline (speedup 1.0000x reference)
#include <cuda_runtime.h>

#define NCTA 128
#define TPB  256
#define CLUSTER 16

typedef unsigned long long u64;

__device__ __forceinline__ void fma2(u64 &d, u64 a, u64 b) {
    asm("fma.rn.f32x2 %0, %1, %2, %0;" : "+l"(d) : "l"(a), "l"(b));
}
__device__ __forceinline__ float hsum(u64 a) {
    union { u64 u; float2 f; } x; x.u = a; return x.f.x + x.f.y;
}
__device__ __forceinline__ float sigm(float x) {
    return __fdividef(1.f, 1.f + __expf(-x));
}
// fast, accurate tanh (no libdevice branches): 2/(1+e^{-2x}) - 1
__device__ __forceinline__ float tanha(float x) {
    return __fdividef(2.f, 1.f + __expf(-2.f * x)) - 1.f;
}

__device__ __forceinline__ unsigned smem_u32(const void *p) {
    unsigned r;
    asm("{ .reg .u64 t1; cvta.to.shared.u64 t1, %1; cvt.u32.u64 %0, t1; }"
        : "=r"(r) : "l"(p));
    return r;
}

// broadcast one float into the same smem offset of all 16 cluster CTAs
__device__ __forceinline__ void bcast16(unsigned laddr, float v) {
#pragma unroll
    for (int p = 0; p < CLUSTER; p++) {
        unsigned ra;
        asm volatile("mapa.shared::cluster.u32 %0, %1, %2;"
                     : "=r"(ra) : "r"(laddr), "r"(p));
        asm volatile("st.shared::cluster.f32 [%0], %1;"
                     :: "r"(ra), "f"(v) : "memory");
    }
}

#define CARRIVE() asm volatile("barrier.cluster.arrive.aligned;" ::: "memory")
#define CWAIT()   asm volatile("barrier.cluster.wait.aligned;"   ::: "memory")

extern __shared__ float sm[];

__global__ __launch_bounds__(TPB, 1)
void regime_kernel(const float *__restrict__ X,    const float *__restrict__ vix,
                   const float *__restrict__ Wih0, const float *__restrict__ Whh0,
                   const float *__restrict__ bih0, const float *__restrict__ bhh0,
                   const float *__restrict__ Wih1, const float *__restrict__ Whh1,
                   const float *__restrict__ bih1, const float *__restrict__ bhh1,
                   const float *__restrict__ lng,  const float *__restrict__ lnb,
                   const float *__restrict__ lw,   const float *__restrict__ lb,
                   const float *__restrict__ rbud, float *__restrict__ out)
{
    float *W0  = sm;                 // 64 rows x 256, swizzled
    float *W1i = sm + 16384;
    float *W1h = sm + 32768;
    float *h0t = sm + 49152;         // 16 x 256 (written by whole cluster)
    float *h1t = sm + 53248;         // 16 x 256
    float *xt  = sm + 57344;         // 16 x 16

    const int t    = threadIdx.x;
    const int bid  = blockIdx.x;
    const int hg   = bid & 15;       // hidden group == cluster rank
    const int bg   = bid >> 4;       // batch group == cluster id
    const int jg   = t & 63;         // (j,gate): jg = 4*j + g
    const int bh   = t >> 6;         // batch quad id (4 batches each)
    const int g    = jg & 3;
    const int j    = jg >> 2;
    const int rot  = jg & 7;
    const int lane = t & 31;
    const int base = lane & ~3;
    const int R    = g * 256 + hg * 16 + j;   // global gate-row

    // ---- zero h tiles (each CTA zeros its own; remote writes only start
    //      after the first cluster barrier, so no race with peers) ----
    for (int f4 = t; f4 < 2048; f4 += TPB)
        ((float4 *)h0t)[f4] = make_float4(0, 0, 0, 0);   // covers h0t + h1t

    // ---- load CTA weight slices into smem, XOR-16B swizzled by row ----
    for (int idx = t; idx < 4096; idx += TPB) {
        int rjg = idx >> 6, q = idx & 63;
        int rr = (rjg & 3) * 256 + hg * 16 + (rjg >> 2);
        int ds = rjg * 256 + ((q ^ (rjg & 7)) << 2);
        *(float4 *)(W0  + ds) = __ldg((const float4 *)(Whh0 + rr * 256 + q * 4));
        *(float4 *)(W1i + ds) = __ldg((const float4 *)(Wih1 + rr * 256 + q * 4));
        *(float4 *)(W1h + ds) = __ldg((const float4 *)(Whh1 + rr * 256 + q * 4));
    }
    // per-thread input weights + fused biases
    float wx[16];
#pragma unroll
    for (int i = 0; i < 16; i += 4) {
        float4 v = __ldg((const float4 *)(Wih0 + R * 16 + i));
        wx[i] = v.x; wx[i + 1] = v.y; wx[i + 2] = v.z; wx[i + 3] = v.w;
    }
    const float b0 = bih0[R] + bhh0[R];
    const float b1 = bih1[R] + bhh1[R];

    float c0[4] = {0, 0, 0, 0}, c1[4] = {0, 0, 0, 0};

    const unsigned h0u = smem_u32(h0t);
    const unsigned h1u = smem_u32(h1t);

    const ulonglong2 *w0p = (const ulonglong2 *)(W0  + jg * 256);
    const ulonglong2 *wip = (const ulonglong2 *)(W1i + jg * 256);
    const ulonglong2 *whp = (const ulonglong2 *)(W1h + jg * 256);
    const ulonglong2 *h0r0 = (const ulonglong2 *)(h0t + (bh * 4 + 0) * 256);
    const ulonglong2 *h0r1 = (const ulonglong2 *)(h0t + (bh * 4 + 1) * 256);
    const ulonglong2 *h0r2 = (const ulonglong2 *)(h0t + (bh * 4 + 2) * 256);
    const ulonglong2 *h0r3 = (const ulonglong2 *)(h0t + (bh * 4 + 3) * 256);
    const ulonglong2 *h1r0 = (const ulonglong2 *)(h1t + (bh * 4 + 0) * 256);
    const ulonglong2 *h1r1 = (const ulonglong2 *)(h1t + (bh * 4 + 1) * 256);
    const ulonglong2 *h1r2 = (const ulonglong2 *)(h1t + (bh * 4 + 2) * 256);
    const ulonglong2 *h1r3 = (const ulonglong2 *)(h1t + (bh * 4 + 3) * 256);

    // ---- main pipelined recurrence: iter k does layer0 step k + layer1 step k-1.
    //      single-buffered h tiles, two cluster barriers per iter:
    //      sync#1 = all CTAs done READING k-1 tiles; sync#2 = k writes visible. ----
    for (int k = 0; k <= 1024; k++) {
        // X for this step (read by gates after sync#1; prev iter's gate reads
        // of xt completed before prev sync#2, so this write is safe)
        if (k < 1024 && t < 64) {
            int bl = t >> 2, i4 = t & 3;
            ((float4 *)xt)[t] =
                __ldg((const float4 *)(X + ((bg * 16 + bl) * 1024 + k) * 16 + i4 * 4));
        }

        u64 a0[4] = {0, 0, 0, 0}, aA[4] = {0, 0, 0, 0}, aB[4] = {0, 0, 0, 0};
#pragma unroll 8
        for (int q = 0; q < 64; q++) {
            const int pq = q ^ rot;
            ulonglong2 w0 = w0p[pq];
            ulonglong2 wi = wip[pq];
            ulonglong2 wh = whp[pq];
            ulonglong2 h, z;
            h = h0r0[q]; z = h1r0[q];
            fma2(a0[0], w0.x, h.x); fma2(a0[0], w0.y, h.y);
            fma2(aA[0], wi.x, h.x); fma2(aA[0], wi.y, h.y);
            fma2(aB[0], wh.x, z.x); fma2(aB[0], wh.y, z.y);
            h = h0r1[q]; z = h1r1[q];
            fma2(a0[1], w0.x, h.x); fma2(a0[1], w0.y, h.y);
            fma2(aA[1], wi.x, h.x); fma2(aA[1], wi.y, h.y);
            fma2(aB[1], wh.x, z.x); fma2(aB[1], wh.y, z.y);
            h = h0r2[q]; z = h1r2[q];
            fma2(a0[2], w0.x, h.x); fma2(a0[2], w0.y, h.y);
            fma2(aA[2], wi.x, h.x); fma2(aA[2], wi.y, h.y);
            fma2(aB[2], wh.x, z.x); fma2(aB[2], wh.y, z.y);
            h = h0r3[q]; z = h1r3[q];
            fma2(a0[3], w0.x, h.x); fma2(a0[3], w0.y, h.y);
            fma2(aA[3], wi.x, h.x); fma2(aA[3], wi.y, h.y);
            fma2(aB[3], wh.x, z.x); fma2(aB[3], wh.y, z.y);
        }

        // sync#1: every CTA in the cluster finished reading the k-1 tiles
        CARRIVE(); CWAIT();

        if (k < 1024) {                      // layer-0 step k
#pragma unroll
            for (int bi = 0; bi < 4; bi++) {
                const float4 *xr = (const float4 *)(xt + (bh * 4 + bi) * 16);
                float xc = 0.f;
#pragma unroll
                for (int i4 = 0; i4 < 4; i4++) {
                    float4 xv = xr[i4];
                    xc += wx[i4 * 4 + 0] * xv.x + wx[i4 * 4 + 1] * xv.y +
                          wx[i4 * 4 + 2] * xv.z + wx[i4 * 4 + 3] * xv.w;
                }
                float v = hsum(a0[bi]) + b0 + xc;
                v = (g == 2) ? tanha(v) : sigm(v);
                float iv = __shfl_sync(0xffffffffu, v, base);
                float fv = __shfl_sync(0xffffffffu, v, base + 1);
                float gv = __shfl_sync(0xffffffffu, v, base + 2);
                float ov = __shfl_sync(0xffffffffu, v, base + 3);
                if (g == 0) {
                    c0[bi] = fv * c0[bi] + iv * gv;
                    float hh = ov * tanha(c0[bi]);
                    bcast16(h0u + (((bh * 4 + bi) << 8) + hg * 16 + j) * 4, hh);
                }
            }
        }
        if (k >= 1) {                        // layer-1 step k-1
#pragma unroll
            for (int bi = 0; bi < 4; bi++) {
                float v = hsum(aA[bi]) + hsum(aB[bi]) + b1;
                v = (g == 2) ? tanha(v) : sigm(v);
                float iv = __shfl_sync(0xffffffffu, v, base);
                float fv = __shfl_sync(0xffffffffu, v, base + 1);
                float gv = __shfl_sync(0xffffffffu, v, base + 2);
                float ov = __shfl_sync(0xffffffffu, v, base + 3);
                if (g == 0) {
                    c1[bi] = fv * c1[bi] + iv * gv;
                    float hh = ov * tanha(c1[bi]);
                    bcast16(h1u + (((bh * 4 + bi) << 8) + hg * 16 + j) * 4, hh);
                }
            }
        }

        // sync#2: all k writes (local + remote DSMEM) visible cluster-wide
        CARRIVE(); CWAIT();
    }

    // ---- head: cluster rank 0 handles its 16 batches from its OWN smem h1 tile
    //      (final sync#2 made h1(step 1023) visible everywhere). ----
    if (hg == 0 && t < 16) {
        const int b = bg * 16 + t;
        const float *h = h1t + t * 256;
        float s = 0.f, s2 = 0.f;
        for (int i = 0; i < 256; i++) { float v = h[i]; s += v; s2 += v * v; }
        float mu  = s * (1.f / 256.f);
        float var = s2 * (1.f / 256.f) - mu * mu;
        float inv = rsqrtf(var + 1e-5f);
        float l0 = lb[0], l1 = lb[1], l2 = lb[2];
        for (int i = 0; i < 256; i++) {
            float v  = h[i];
            float hn = (v - mu) * inv * lng[i] + lnb[i];
            l0 += hn * lw[i]; l1 += hn * lw[256 + i]; l2 += hn * lw[512 + i];
        }
        float m  = fmaxf(l0, fmaxf(l1, l2));
        float e0 = __expf(l0 - m), e1 = __expf(l1 - m), e2 = __expf(l2 - m);
        float es = e0 + e1 + e2;
        float p0 = e0 / es, p1 = e1 / es, p2 = e2 / es;

        float bm[3], bs[3];
#pragma unroll
        for (int r = 0; r < 3; r++) {
            float mm = -1e30f;
            for (int p = 0; p < 32; p++) mm = fmaxf(mm, rbud[r * 32 + p]);
            float sx = 0.f;
            for (int p = 0; p < 32; p++) sx += __expf(rbud[r * 32 + p] - mm);
            bm[r] = mm; bs[r] = sx;
        }
        float w0s = p0 / bs[0], w1s = p1 / bs[1], w2s = p2 / bs[2];
        float bb[32];
        float eqs = 0.f, dfs = 0.f;
        for (int p = 0; p < 32; p++) {
            float v = w0s * __expf(rbud[p]      - bm[0]) +
                      w1s * __expf(rbud[32 + p] - bm[1]) +
                      w2s * __expf(rbud[64 + p] - bm[2]);
            bb[p] = v;
            if (p < 24) eqs += v; else dfs += v;
        }
        bool  mask      = vix[b] >= 30.0f;
        float shortfall = 0.4f - dfs;
        float ratio     = fminf(shortfall / fmaxf(eqs, 1e-8f), 0.8f);
        bool  apply     = mask && (shortfall > 0.f) && (eqs > 1e-8f);
        float bsel[32], bsum = 0.f;
        for (int p = 0; p < 32; p++) {
            float b2 = (p < 24) ? bb[p] * (1.f - ratio) : bb[p] + shortfall * (1.f / 8.f);
            float v  = apply ? b2 : bb[p];
            bsel[p] = v; bsum += v;
        }
        float innorm = 1.f / (bsum + 1e-8f);
        for (int p = 0; p < 32; p++)
            out[b * 32 + p] = mask ? bsel[p] * innorm : bb[p];
        out[4096 + b * 3 + 0] = p0;
        out[4096 + b * 3 + 1] = p1;
        out[4096 + b * 3 + 2] = p2;
    }

    // final cluster barrier: no CTA exits while a peer might still be reading
    // its smem (rank-0 head reads only its OWN tile, but keep teardown clean)
    CARRIVE(); CWAIT();
}

extern "C" void kernel_launch(void *const *d_in, const int *in_sizes, int n_in,
                              void *d_out, int out_size)
{
    (void)in_sizes; (void)n_in; (void)out_size;
    static int inited = 0;
    const int smem = 57600 * 4;   // 230400 B
    if (!inited) {
        cudaFuncSetAttribute(regime_kernel,
                             cudaFuncAttributeMaxDynamicSharedMemorySize, smem);
        cudaFuncSetAttribute(regime_kernel,
                             cudaFuncAttributeNonPortableClusterSizeAllowed, 1);
        inited = 1;
    }
    cudaLaunchConfig_t cfg = {};
    cfg.gridDim         = dim3(NCTA, 1, 1);
    cfg.blockDim        = dim3(TPB, 1, 1);
    cfg.dynamicSmemBytes = smem;
    cfg.stream          = 0;
    cudaLaunchAttribute attrs[1];
    attrs[0].id = cudaLaunchAttributeClusterDimension;
    attrs[0].val.clusterDim.x = CLUSTER;
    attrs[0].val.clusterDim.y = 1;
    attrs[0].val.clusterDim.z = 1;
    cfg.attrs    = attrs;
    cfg.numAttrs = 1;
    cudaLaunchKernelEx(&cfg, regime_kernel,
        (const float *)d_in[0],  (const float *)d_in[1],  (const float *)d_in[2],
        (const float *)d_in[3],  (const float *)d_in[4],  (const float *)d_in[5],
        (const float *)d_in[6],  (const float *)d_in[7],  (const float *)d_in[8],
        (const float *)d_in[9],  (const float *)d_in[10], (const float *)d_in[11],
        (const float *)d_in[12], (const float *)d_in[13], (const float *)d_in[14],
        (float *)d_out);
}

// round 15
// speedup vs baseline: 1.0005x; 1.0005x over previous
#include <cuda_runtime.h>

#define NCTA 128
#define TPB  256
#define CLUSTER 16

typedef unsigned long long u64;

__device__ __forceinline__ void fma2(u64 &d, u64 a, u64 b) {
    asm("fma.rn.f32x2 %0, %1, %2, %0;" : "+l"(d) : "l"(a), "l"(b));
}
__device__ __forceinline__ float hsum(u64 a) {
    union { u64 u; float2 f; } x; x.u = a; return x.f.x + x.f.y;
}
__device__ __forceinline__ float sigm(float x) {
    return __fdividef(1.f, 1.f + __expf(-x));
}
// fast, accurate tanh (no libdevice branches): 2/(1+e^{-2x}) - 1
__device__ __forceinline__ float tanha(float x) {
    return __fdividef(2.f, 1.f + __expf(-2.f * x)) - 1.f;
}

__device__ __forceinline__ unsigned smem_u32(const void *p) {
    unsigned r;
    asm("{ .reg .u64 t1; cvta.to.shared.u64 t1, %1; cvt.u32.u64 %0, t1; }"
        : "=r"(r) : "l"(p));
    return r;
}

// broadcast one float into the same smem offset of all 16 cluster CTAs
__device__ __forceinline__ void bcast16(unsigned laddr, float v) {
#pragma unroll
    for (int p = 0; p < CLUSTER; p++) {
        unsigned ra;
        asm volatile("mapa.shared::cluster.u32 %0, %1, %2;"
                     : "=r"(ra) : "r"(laddr), "r"(p));
        asm volatile("st.shared::cluster.f32 [%0], %1;"
                     :: "r"(ra), "f"(v) : "memory");
    }
}

#define CARRIVE() asm volatile("barrier.cluster.arrive.aligned;" ::: "memory")
#define CWAIT()   asm volatile("barrier.cluster.wait.aligned;"   ::: "memory")

extern __shared__ float sm[];

__global__ __launch_bounds__(TPB, 1)
void regime_kernel(const float *__restrict__ X,    const float *__restrict__ vix,
                   const float *__restrict__ Wih0, const float *__restrict__ Whh0,
                   const float *__restrict__ bih0, const float *__restrict__ bhh0,
                   const float *__restrict__ Wih1, const float *__restrict__ Whh1,
                   const float *__restrict__ bih1, const float *__restrict__ bhh1,
                   const float *__restrict__ lng,  const float *__restrict__ lnb,
                   const float *__restrict__ lw,   const float *__restrict__ lb,
                   const float *__restrict__ rbud, float *__restrict__ out)
{
    float *W0  = sm;                 // 64 rows x 256, swizzled
    float *W1i = sm + 16384;
    float *W1h = sm + 32768;
    float *h0t = sm + 49152;         // 16 x 256 (written by whole cluster)
    float *h1t = sm + 53248;         // 16 x 256
    float *xt  = sm + 57344;         // 16 x 16

    const int t    = threadIdx.x;
    const int bid  = blockIdx.x;
    const int hg   = bid & 15;       // hidden group == cluster rank
    const int bg   = bid >> 4;       // batch group == cluster id
    const int jg   = t & 63;         // (j,gate): jg = 4*j + g
    const int bh   = t >> 6;         // batch quad id (4 batches each)
    const int g    = jg & 3;
    const int j    = jg >> 2;
    const int rot  = jg & 7;
    const int lane = t & 31;
    const int base = lane & ~3;
    const int R    = g * 256 + hg * 16 + j;   // global gate-row

    // ---- zero h tiles (each CTA zeros its own; remote writes only start
    //      after the first cluster barrier, so no race with peers) ----
    for (int f4 = t; f4 < 2048; f4 += TPB)
        ((float4 *)h0t)[f4] = make_float4(0, 0, 0, 0);   // covers h0t + h1t

    // ---- load CTA weight slices into smem, XOR-16B swizzled by row ----
    for (int idx = t; idx < 4096; idx += TPB) {
        int rjg = idx >> 6, q = idx & 63;
        int rr = (rjg & 3) * 256 + hg * 16 + (rjg >> 2);
        int ds = rjg * 256 + ((q ^ (rjg & 7)) << 2);
        *(float4 *)(W0  + ds) = __ldg((const float4 *)(Whh0 + rr * 256 + q * 4));
        *(float4 *)(W1i + ds) = __ldg((const float4 *)(Wih1 + rr * 256 + q * 4));
        *(float4 *)(W1h + ds) = __ldg((const float4 *)(Whh1 + rr * 256 + q * 4));
    }
    // per-thread input weights + fused biases
    float wx[16];
#pragma unroll
    for (int i = 0; i < 16; i += 4) {
        float4 v = __ldg((const float4 *)(Wih0 + R * 16 + i));
        wx[i] = v.x; wx[i + 1] = v.y; wx[i + 2] = v.z; wx[i + 3] = v.w;
    }
    const float b0 = bih0[R] + bhh0[R];
    const float b1 = bih1[R] + bhh1[R];

    float c0[4] = {0, 0, 0, 0}, c1[4] = {0, 0, 0, 0};

    const unsigned h0u = smem_u32(h0t);
    const unsigned h1u = smem_u32(h1t);

    const ulonglong2 *w0p = (const ulonglong2 *)(W0  + jg * 256);
    const ulonglong2 *wip = (const ulonglong2 *)(W1i + jg * 256);
    const ulonglong2 *whp = (const ulonglong2 *)(W1h + jg * 256);
    const ulonglong2 *h0r0 = (const ulonglong2 *)(h0t + (bh * 4 + 0) * 256);
    const ulonglong2 *h0r1 = (const ulonglong2 *)(h0t + (bh * 4 + 1) * 256);
    const ulonglong2 *h0r2 = (const ulonglong2 *)(h0t + (bh * 4 + 2) * 256);
    const ulonglong2 *h0r3 = (const ulonglong2 *)(h0t + (bh * 4 + 3) * 256);
    const ulonglong2 *h1r0 = (const ulonglong2 *)(h1t + (bh * 4 + 0) * 256);
    const ulonglong2 *h1r1 = (const ulonglong2 *)(h1t + (bh * 4 + 1) * 256);
    const ulonglong2 *h1r2 = (const ulonglong2 *)(h1t + (bh * 4 + 2) * 256);
    const ulonglong2 *h1r3 = (const ulonglong2 *)(h1t + (bh * 4 + 3) * 256);

    // ---- main pipelined recurrence: iter k does layer0 step k + layer1 step k-1.
    //      single-buffered h tiles, two cluster barriers per iter:
    //      sync#1 = all CTAs done READING k-1 tiles; sync#2 = k writes visible. ----
    for (int k = 0; k <= 1024; k++) {
        // X for this step (read by gates after sync#1; prev iter's gate reads
        // of xt completed before prev sync#2, so this write is safe)
        if (k < 1024 && t < 64) {
            int bl = t >> 2, i4 = t & 3;
            ((float4 *)xt)[t] =
                __ldg((const float4 *)(X + ((bg * 16 + bl) * 1024 + k) * 16 + i4 * 4));
        }

        u64 a0[4] = {0, 0, 0, 0}, aA[4] = {0, 0, 0, 0}, aB[4] = {0, 0, 0, 0};
#pragma unroll 8
        for (int q = 0; q < 64; q++) {
            const int pq = q ^ rot;
            ulonglong2 w0 = w0p[pq];
            ulonglong2 wi = wip[pq];
            ulonglong2 wh = whp[pq];
            ulonglong2 h, z;
            h = h0r0[q]; z = h1r0[q];
            fma2(a0[0], w0.x, h.x); fma2(a0[0], w0.y, h.y);
            fma2(aA[0], wi.x, h.x); fma2(aA[0], wi.y, h.y);
            fma2(aB[0], wh.x, z.x); fma2(aB[0], wh.y, z.y);
            h = h0r1[q]; z = h1r1[q];
            fma2(a0[1], w0.x, h.x); fma2(a0[1], w0.y, h.y);
            fma2(aA[1], wi.x, h.x); fma2(aA[1], wi.y, h.y);
            fma2(aB[1], wh.x, z.x); fma2(aB[1], wh.y, z.y);
            h = h0r2[q]; z = h1r2[q];
            fma2(a0[2], w0.x, h.x); fma2(a0[2], w0.y, h.y);
            fma2(aA[2], wi.x, h.x); fma2(aA[2], wi.y, h.y);
            fma2(aB[2], wh.x, z.x); fma2(aB[2], wh.y, z.y);
            h = h0r3[q]; z = h1r3[q];
            fma2(a0[3], w0.x, h.x); fma2(a0[3], w0.y, h.y);
            fma2(aA[3], wi.x, h.x); fma2(aA[3], wi.y, h.y);
            fma2(aB[3], wh.x, z.x); fma2(aB[3], wh.y, z.y);
        }

        // sync#1: every CTA in the cluster finished reading the k-1 tiles
        CARRIVE(); CWAIT();

        if (k < 1024) {                      // layer-0 step k
#pragma unroll
            for (int bi = 0; bi < 4; bi++) {
                const float4 *xr = (const float4 *)(xt + (bh * 4 + bi) * 16);
                float xc = 0.f;
#pragma unroll
                for (int i4 = 0; i4 < 4; i4++) {
                    float4 xv = xr[i4];
                    xc += wx[i4 * 4 + 0] * xv.x + wx[i4 * 4 + 1] * xv.y +
                          wx[i4 * 4 + 2] * xv.z + wx[i4 * 4 + 3] * xv.w;
                }
                float v = hsum(a0[bi]) + b0 + xc;
                v = (g == 2) ? tanha(v) : sigm(v);
                float iv = __shfl_sync(0xffffffffu, v, base);
                float fv = __shfl_sync(0xffffffffu, v, base + 1);
                float gv = __shfl_sync(0xffffffffu, v, base + 2);
                float ov = __shfl_sync(0xffffffffu, v, base + 3);
                if (g == 0) {
                    c0[bi] = fv * c0[bi] + iv * gv;
                    float hh = ov * tanha(c0[bi]);
                    bcast16(h0u + (((bh * 4 + bi) << 8) + hg * 16 + j) * 4, hh);
                }
            }
        }
        if (k >= 1) {                        // layer-1 step k-1
#pragma unroll
            for (int bi = 0; bi < 4; bi++) {
                float v = hsum(aA[bi]) + hsum(aB[bi]) + b1;
                v = (g == 2) ? tanha(v) : sigm(v);
                float iv = __shfl_sync(0xffffffffu, v, base);
                float fv = __shfl_sync(0xffffffffu, v, base + 1);
                float gv = __shfl_sync(0xffffffffu, v, base + 2);
                float ov = __shfl_sync(0xffffffffu, v, base + 3);
                if (g == 0) {
                    c1[bi] = fv * c1[bi] + iv * gv;
                    float hh = ov * tanha(c1[bi]);
                    bcast16(h1u + (((bh * 4 + bi) << 8) + hg * 16 + j) * 4, hh);
                }
            }
        }

        // sync#2: all k writes (local + remote DSMEM) visible cluster-wide
        CARRIVE(); CWAIT();
    }

    // ---- head: cluster rank 0 handles its 16 batches from its OWN smem h1 tile
    //      (final sync#2 made h1(step 1023) visible everywhere). ----
    if (hg == 0 && t < 16) {
        const int b = bg * 16 + t;
        const float *h = h1t + t * 256;
        float s = 0.f, s2 = 0.f;
        for (int i = 0; i < 256; i++) { float v = h[i]; s += v; s2 += v * v; }
        float mu  = s * (1.f / 256.f);
        float var = s2 * (1.f / 256.f) - mu * mu;
        float inv = rsqrtf(var + 1e-5f);
        float l0 = lb[0], l1 = lb[1], l2 = lb[2];
        for (int i = 0; i < 256; i++) {
            float v  = h[i];
            float hn = (v - mu) * inv * lng[i] + lnb[i];
            l0 += hn * lw[i]; l1 += hn * lw[256 + i]; l2 += hn * lw[512 + i];
        }
        float m  = fmaxf(l0, fmaxf(l1, l2));
        float e0 = __expf(l0 - m), e1 = __expf(l1 - m), e2 = __expf(l2 - m);
        float es = e0 + e1 + e2;
        float p0 = e0 / es, p1 = e1 / es, p2 = e2 / es;

        float bm[3], bs[3];
#pragma unroll
        for (int r = 0; r < 3; r++) {
            float mm = -1e30f;
            for (int p = 0; p < 32; p++) mm = fmaxf(mm, rbud[r * 32 + p]);
            float sx = 0.f;
            for (int p = 0; p < 32; p++) sx += __expf(rbud[r * 32 + p] - mm);
            bm[r] = mm; bs[r] = sx;
        }
        float w0s = p0 / bs[0], w1s = p1 / bs[1], w2s = p2 / bs[2];
        float bb[32];
        float eqs = 0.f, dfs = 0.f;
        for (int p = 0; p < 32; p++) {
            float v = w0s * __expf(rbud[p]      - bm[0]) +
                      w1s * __expf(rbud[32 + p] - bm[1]) +
                      w2s * __expf(rbud[64 + p] - bm[2]);
            bb[p] = v;
            if (p < 24) eqs += v; else dfs += v;
        }
        bool  mask      = vix[b] >= 30.0f;
        float shortfall = 0.4f - dfs;
        float ratio     = fminf(shortfall / fmaxf(eqs, 1e-8f), 0.8f);
        bool  apply     = mask && (shortfall > 0.f) && (eqs > 1e-8f);
        float bsel[32], bsum = 0.f;
        for (int p = 0; p < 32; p++) {
            float b2 = (p < 24) ? bb[p] * (1.f - ratio) : bb[p] + shortfall * (1.f / 8.f);
            float v  = apply ? b2 : bb[p];
            bsel[p] = v; bsum += v;
        }
        float innorm = 1.f / (bsum + 1e-8f);
        for (int p = 0; p < 32; p++)
            out[b * 32 + p] = mask ? bsel[p] * innorm : bb[p];
        out[4096 + b * 3 + 0] = p0;
        out[4096 + b * 3 + 1] = p1;
        out[4096 + b * 3 + 2] = p2;
    }

    // final cluster barrier: no CTA exits while a peer might still be reading
    // its smem (rank-0 head reads only its OWN tile, but keep teardown clean)
    CARRIVE(); CWAIT();
}

extern "C" void kernel_launch(void *const *d_in, const int *in_sizes, int n_in,
                              void *d_out, int out_size)
{
    (void)in_sizes; (void)n_in; (void)out_size;
    static int inited = 0;
    const int smem = 57600 * 4;   // 230400 B
    if (!inited) {
        cudaFuncSetAttribute(regime_kernel,
                             cudaFuncAttributeMaxDynamicSharedMemorySize, smem);
        cudaFuncSetAttribute(regime_kernel,
                             cudaFuncAttributeNonPortableClusterSizeAllowed, 1);
        inited = 1;
    }
    cudaLaunchConfig_t cfg = {};
    cfg.gridDim         = dim3(NCTA, 1, 1);
    cfg.blockDim        = dim3(TPB, 1, 1);
    cfg.dynamicSmemBytes = smem;
    cfg.stream          = 0;
    cudaLaunchAttribute attrs[1];
    attrs[0].id = cudaLaunchAttributeClusterDimension;
    attrs[0].val.clusterDim.x = CLUSTER;
    attrs[0].val.clusterDim.y = 1;
    attrs[0].val.clusterDim.z = 1;
    cfg.attrs    = attrs;
    cfg.numAttrs = 1;
    cudaLaunchKernelEx(&cfg, regime_kernel,
        (const float *)d_in[0],  (const float *)d_in[1],  (const float *)d_in[2],
        (const float *)d_in[3],  (const float *)d_in[4],  (const float *)d_in[5],
        (const float *)d_in[6],  (const float *)d_in[7],  (const float *)d_in[8],
        (const float *)d_in[9],  (const float *)d_in[10], (const float *)d_in[11],
        (const float *)d_in[12], (const float *)d_in[13], (const float *)d_in[14],
        (float *)d_out);
}

// round 16
// speedup vs baseline: 3.7342x; 3.7323x over previous
#include <cuda_runtime.h>
#include <cuda_bf16.h>

#define NCTA 128
#define TPB  256
#define OB0H 0
#define OB0L 32768
#define OB1H 65536
#define OB1L 131072
#define OAH  196608
#define OAL  212992
#define OXT  229376
#define SMEMB 230400

__device__ unsigned g_h0[2][128][256];
__device__ unsigned g_h1[2][128][256];
__device__ unsigned g_grp[8];

__device__ __forceinline__ float sigm(float x){ return __fdividef(1.f,1.f+__expf(-x)); }
__device__ __forceinline__ float tanha(float x){ return __fdividef(2.f,1.f+__expf(-2.f*x))-1.f; }
__device__ __forceinline__ unsigned packh(float v){
    __nv_bfloat16 hi = __float2bfloat16(v);
    __nv_bfloat16 lo = __float2bfloat16(v - __bfloat162float(hi));
    return (unsigned)__bfloat16_as_ushort(hi) | ((unsigned)__bfloat16_as_ushort(lo)<<16);
}
__device__ __forceinline__ float unpackh(unsigned u){
    return __bfloat162float(__ushort_as_bfloat16((unsigned short)(u&0xffffu))) +
           __bfloat162float(__ushort_as_bfloat16((unsigned short)(u>>16)));
}
__device__ __forceinline__ unsigned smem_u32(const void *p){
    unsigned r;
    asm("{ .reg .u64 t1; cvta.to.shared.u64 t1, %1; cvt.u32.u64 %0, t1; }" : "=r"(r) : "l"(p));
    return r;
}
__device__ __forceinline__ void ldsm4(unsigned *r, unsigned a){
    asm volatile("ldmatrix.sync.aligned.m8n8.x4.shared.b16 {%0,%1,%2,%3}, [%4];"
                 : "=r"(r[0]),"=r"(r[1]),"=r"(r[2]),"=r"(r[3]) : "r"(a));
}
__device__ __forceinline__ void mma(float *d, const unsigned *a, const unsigned *b){
    asm volatile("mma.sync.aligned.m16n8k16.row.col.f32.bf16.bf16.f32 "
                 "{%0,%1,%2,%3}, {%4,%5,%6,%7}, {%8,%9}, {%0,%1,%2,%3};"
                 : "+f"(d[0]),"+f"(d[1]),"+f"(d[2]),"+f"(d[3])
                 : "r"(a[0]),"r"(a[1]),"r"(a[2]),"r"(a[3]), "r"(b[0]),"r"(b[1]));
}
__device__ __forceinline__ void grp_arrive(int bg){
    asm volatile("red.release.gpu.global.add.u32 [%0], %1;" :: "l"(&g_grp[bg]), "r"(1u) : "memory");
}
__device__ __forceinline__ void grp_wait(int bg, unsigned tgt){
    unsigned v, ns = 32;
    for(;;){
        asm volatile("ld.acquire.gpu.global.u32 %0, [%1];" : "=r"(v) : "l"(&g_grp[bg]) : "memory");
        if (v >= tgt) break;
        __nanosleep(ns); if (ns < 256) ns <<= 1;
    }
}
__device__ __forceinline__ void groupbar(int bg, unsigned tgt){
    __syncthreads();
    if (threadIdx.x == 0){ grp_arrive(bg); grp_wait(bg, tgt); }
    __syncthreads();
}

extern __shared__ char smb[];

__global__ __launch_bounds__(TPB, 1)
void regime_kernel(const float *__restrict__ X,    const float *__restrict__ vix,
                   const float *__restrict__ Wih0, const float *__restrict__ Whh0,
                   const float *__restrict__ bih0, const float *__restrict__ bhh0,
                   const float *__restrict__ Wih1, const float *__restrict__ Whh1,
                   const float *__restrict__ bih1, const float *__restrict__ bhh1,
                   const float *__restrict__ lng,  const float *__restrict__ lnb,
                   const float *__restrict__ lw,   const float *__restrict__ lb,
                   const float *__restrict__ rbud, float *__restrict__ out)
{
    const int t    = threadIdx.x;
    const int bid  = blockIdx.x;
    const int hg   = bid & 15;
    const int bg   = bid >> 4;
    const int w    = t >> 5;
    const int lane = t & 31;
    float *xtf = (float *)(smb + OXT);

    // ---- one-time weight conversion into swizzled bf16 hi/lo smem tiles ----
    // B0 row n -> Whh0 row R=(n&3)*256 + hg*16 + (n>>2), pitch 512B
    for (int idx = t; idx < 16384; idx += TPB) {
        int n = idx >> 8, kk = idx & 255;
        int R = (n & 3) * 256 + hg * 16 + (n >> 2);
        float v = __ldg(Whh0 + R * 256 + kk);
        __nv_bfloat16 hi = __float2bfloat16(v);
        __nv_bfloat16 lo = __float2bfloat16(v - __bfloat162float(hi));
        int off = ((n << 9) + (kk << 1)) ^ ((n & 7) << 4);
        *(__nv_bfloat16 *)(smb + OB0H + off) = hi;
        *(__nv_bfloat16 *)(smb + OB0L + off) = lo;
    }
    // B1 row n: k<256 -> Wih1, k>=256 -> Whh1, pitch 1024B
    for (int idx = t; idx < 32768; idx += TPB) {
        int n = idx >> 9, kk = idx & 511;
        int R = (n & 3) * 256 + hg * 16 + (n >> 2);
        float v = (kk < 256) ? __ldg(Wih1 + R * 256 + kk) : __ldg(Whh1 + R * 256 + kk - 256);
        __nv_bfloat16 hi = __float2bfloat16(v);
        __nv_bfloat16 lo = __float2bfloat16(v - __bfloat162float(hi));
        int off = ((n << 10) + (kk << 1)) ^ ((n & 7) << 4);
        *(__nv_bfloat16 *)(smb + OB1H + off) = hi;
        *(__nv_bfloat16 *)(smb + OB1L + off) = lo;
    }

    // per-lane column identities: q = lane&3 -> B cols n0=2q, n0+1 of this warp's tile
    const int q   = lane & 3;
    const int n0  = 2 * q;
    const int R0  = (n0 & 3) * 256 + hg * 16 + (2 * w + (n0 >> 2));
    const int R1  = ((n0 + 1) & 3) * 256 + hg * 16 + (2 * w + ((n0 + 1) >> 2));
    const int r   = lane >> 2;                 // batch r and r+8
    const int jl  = 2 * w + (q >> 1);          // within-CTA hidden index
    const bool oddq = (q & 1) != 0;
    float wx0[16], wx1[16];
#pragma unroll
    for (int i = 0; i < 16; i++) { wx0[i] = __ldg(Wih0 + R0 * 16 + i); wx1[i] = __ldg(Wih0 + R1 * 16 + i); }
    const float bb00 = bih0[R0] + bhh0[R0], bb01 = bih0[R1] + bhh0[R1];
    const float bb10 = bih1[R0] + bhh1[R0], bb11 = bih1[R1] + bhh1[R1];
    float cs0[2] = {0, 0}, cs1[2] = {0, 0};

    // ldmatrix addressing
    const unsigned smu = smem_u32(smb);
    const int sub = lane >> 3;
    const int arr = (sub & 1) * 8 + (lane & 7);        // A row
    const int akh = (sub >> 1) * 8;                    // A k-subtile
    const unsigned aswz = (unsigned)((arr & 7) << 4);
    const unsigned aBH = smu + OAH + (arr << 10), aBL = smu + OAL + (arr << 10);
    const int brw = lane & 7, btk = (lane >> 3) * 8;
    const unsigned bswz = (unsigned)(brw << 4);
    const unsigned b1BH = smu + OB1H + ((8 * w + brw) << 10);
    const unsigned b1BL = smu + OB1L + ((8 * w + brw) << 10);
    const unsigned b0BH = smu + OB0H + ((8 * w + brw) << 9);
    const unsigned b0BL = smu + OB0L + ((8 * w + brw) << 9);
    __syncthreads();

    for (int k = 0; k <= 1024; k++) {
        const int pp = (k - 1) & 1;
        // ---- stage packed h -> A hi/lo tiles (pitch 1024B, swizzled), + x ----
        {
            const int b = t >> 4, ch = t & 15;
            uint4 qa[4], qb[4];
            if (k > 0) {
                const uint4 *s = (const uint4 *)&g_h0[pp][bg * 16 + b][ch * 16];
                qa[0]=__ldcg(s); qa[1]=__ldcg(s+1); qa[2]=__ldcg(s+2); qa[3]=__ldcg(s+3);
            } else qa[0]=qa[1]=qa[2]=qa[3]=make_uint4(0,0,0,0);
            if (k > 1) {
                const uint4 *s = (const uint4 *)&g_h1[pp][bg * 16 + b][ch * 16];
                qb[0]=__ldcg(s); qb[1]=__ldcg(s+1); qb[2]=__ldcg(s+2); qb[3]=__ldcg(s+3);
            } else qb[0]=qb[1]=qb[2]=qb[3]=make_uint4(0,0,0,0);
            const int swz = (b & 7) << 4;
#pragma unroll
            for (int c = 0; c < 4; c++) {
                int kb = ch * 16 + c * 4;
                int o0 = ((b << 10) + (kb << 1)) ^ swz;
                int o1 = ((b << 10) + ((kb + 2) << 1)) ^ swz;
                *(unsigned *)(smb + OAH + o0) = __byte_perm(qa[c].x, qa[c].y, 0x5410);
                *(unsigned *)(smb + OAL + o0) = __byte_perm(qa[c].x, qa[c].y, 0x7632);
                *(unsigned *)(smb + OAH + o1) = __byte_perm(qa[c].z, qa[c].w, 0x5410);
                *(unsigned *)(smb + OAL + o1) = __byte_perm(qa[c].z, qa[c].w, 0x7632);
                int k2 = 256 + kb;
                int o2 = ((b << 10) + (k2 << 1)) ^ swz;
                int o3 = ((b << 10) + ((k2 + 2) << 1)) ^ swz;
                *(unsigned *)(smb + OAH + o2) = __byte_perm(qb[c].x, qb[c].y, 0x5410);
                *(unsigned *)(smb + OAL + o2) = __byte_perm(qb[c].x, qb[c].y, 0x7632);
                *(unsigned *)(smb + OAH + o3) = __byte_perm(qb[c].z, qb[c].w, 0x5410);
                *(unsigned *)(smb + OAL + o3) = __byte_perm(qb[c].z, qb[c].w, 0x7632);
            }
        }
        if (k < 1024 && t < 64) {
            int bl = t >> 2, i4 = t & 3;
            ((float4 *)xtf)[t] = __ldg((const float4 *)(X + ((bg * 16 + bl) * 1024 + k) * 16 + i4 * 4));
        }
        __syncthreads();

        // ---- MMA: d0 = Whh0·h0 (K 0..255); d1 = Wih1·h0 + Whh1·h1 (K 0..511) ----
        float d0[4] = {0,0,0,0}, d1[4] = {0,0,0,0};
#pragma unroll 2
        for (int c2 = 0; c2 < 8; c2++) {
            const int kw = c2 << 5;
            unsigned A0h[4],A1h[4],A0l[4],A1l[4],B1h[4],B1l[4],B0h[4],B0l[4];
            ldsm4(A0h, (aBH + ((kw + akh) << 1)) ^ aswz);
            ldsm4(A1h, (aBH + ((kw + 16 + akh) << 1)) ^ aswz);
            ldsm4(A0l, (aBL + ((kw + akh) << 1)) ^ aswz);
            ldsm4(A1l, (aBL + ((kw + 16 + akh) << 1)) ^ aswz);
            ldsm4(B1h, (b1BH + ((kw + btk) << 1)) ^ bswz);
            ldsm4(B1l, (b1BL + ((kw + btk) << 1)) ^ bswz);
            ldsm4(B0h, (b0BH + ((kw + btk) << 1)) ^ bswz);
            ldsm4(B0l, (b0BL + ((kw + btk) << 1)) ^ bswz);
            mma(d1, A0h, &B1h[0]); mma(d1, A0h, &B1l[0]); mma(d1, A0l, &B1h[0]);
            mma(d1, A1h, &B1h[2]); mma(d1, A1h, &B1l[2]); mma(d1, A1l, &B1h[2]);
            mma(d0, A0h, &B0h[0]); mma(d0, A0h, &B0l[0]); mma(d0, A0l, &B0h[0]);
            mma(d0, A1h, &B0h[2]); mma(d0, A1h, &B0l[2]); mma(d0, A1l, &B0h[2]);
        }
#pragma unroll 2
        for (int c2 = 8; c2 < 16; c2++) {
            const int kw = c2 << 5;
            unsigned A0h[4],A1h[4],A0l[4],A1l[4],B1h[4],B1l[4];
            ldsm4(A0h, (aBH + ((kw + akh) << 1)) ^ aswz);
            ldsm4(A1h, (aBH + ((kw + 16 + akh) << 1)) ^ aswz);
            ldsm4(A0l, (aBL + ((kw + akh) << 1)) ^ aswz);
            ldsm4(A1l, (aBL + ((kw + 16 + akh) << 1)) ^ aswz);
            ldsm4(B1h, (b1BH + ((kw + btk) << 1)) ^ bswz);
            ldsm4(B1l, (b1BL + ((kw + btk) << 1)) ^ bswz);
            mma(d1, A0h, &B1h[0]); mma(d1, A0h, &B1l[0]); mma(d1, A0l, &B1h[0]);
            mma(d1, A1h, &B1h[2]); mma(d1, A1h, &B1l[2]); mma(d1, A1l, &B1h[2]);
        }

        // ---- epilogue: even-q lanes hold (i,f), odd-q (g,o); shfl_xor(1) pairs ----
        if (k < 1024) {
            const float *xr0 = xtf + r * 16, *xr8 = xtf + (r + 8) * 16;
            float x00=0, x01=0, x80=0, x81=0;
#pragma unroll
            for (int i = 0; i < 16; i++) {
                float a = xr0[i], b8 = xr8[i];
                x00 += wx0[i]*a; x01 += wx1[i]*a; x80 += wx0[i]*b8; x81 += wx1[i]*b8;
            }
            float e0 = d0[0]+bb00+x00, e1 = d0[1]+bb01+x01;
            float e2 = d0[2]+bb00+x80, e3 = d0[3]+bb01+x81;
            float a0 = oddq ? tanha(e0) : sigm(e0);
            float a1 = sigm(e1);
            float a2 = oddq ? tanha(e2) : sigm(e2);
            float a3 = sigm(e3);
            float p0 = __shfl_xor_sync(0xffffffffu, a0, 1);
            float p1 = __shfl_xor_sync(0xffffffffu, a1, 1);
            float p2 = __shfl_xor_sync(0xffffffffu, a2, 1);
            float p3 = __shfl_xor_sync(0xffffffffu, a3, 1);
            if (!oddq) {
                cs0[0] = a1 * cs0[0] + a0 * p0;
                cs0[1] = a3 * cs0[1] + a2 * p2;
                __stcg(&g_h0[k & 1][bg*16 + r][hg*16 + jl],     packh(p1 * tanha(cs0[0])));
                __stcg(&g_h0[k & 1][bg*16 + r + 8][hg*16 + jl], packh(p3 * tanha(cs0[1])));
            }
        }
        if (k >= 1) {
            float e0 = d1[0]+bb10, e1 = d1[1]+bb11, e2 = d1[2]+bb10, e3 = d1[3]+bb11;
            float a0 = oddq ? tanha(e0) : sigm(e0);
            float a1 = sigm(e1);
            float a2 = oddq ? tanha(e2) : sigm(e2);
            float a3 = sigm(e3);
            float p0 = __shfl_xor_sync(0xffffffffu, a0, 1);
            float p1 = __shfl_xor_sync(0xffffffffu, a1, 1);
            float p2 = __shfl_xor_sync(0xffffffffu, a2, 1);
            float p3 = __shfl_xor_sync(0xffffffffu, a3, 1);
            if (!oddq) {
                cs1[0] = a1 * cs1[0] + a0 * p0;
                cs1[1] = a3 * cs1[1] + a2 * p2;
                __stcg(&g_h1[k & 1][bg*16 + r][hg*16 + jl],     packh(p1 * tanha(cs1[0])));
                __stcg(&g_h1[k & 1][bg*16 + r + 8][hg*16 + jl], packh(p3 * tanha(cs1[1])));
            }
        }
        groupbar(bg, 16u * (unsigned)(k + 1));
    }

    if (t == 0) grp_arrive(bg);   // done-pass for reset

    // ---- head on hg==0 CTA (data visible after final groupbar) ----
    if (hg == 0) {
        if (t < 16) {
            const int b = bg * 16 + t;
            const unsigned *hp = &g_h1[0][b][0];
            float hv[256];
            float s = 0.f, s2 = 0.f;
            for (int i = 0; i < 256; i++) { float v = unpackh(__ldcg(hp + i)); hv[i] = v; s += v; s2 += v * v; }
            float mu  = s * (1.f/256.f);
            float var = s2 * (1.f/256.f) - mu * mu;
            float inv = rsqrtf(var + 1e-5f);
            float l0 = lb[0], l1 = lb[1], l2 = lb[2];
            for (int i = 0; i < 256; i++) {
                float hn = (hv[i] - mu) * inv * lng[i] + lnb[i];
                l0 += hn * lw[i]; l1 += hn * lw[256 + i]; l2 += hn * lw[512 + i];
            }
            float m  = fmaxf(l0, fmaxf(l1, l2));
            float e0 = __expf(l0-m), e1 = __expf(l1-m), e2 = __expf(l2-m);
            float es = e0 + e1 + e2;
            float p0 = e0/es, p1 = e1/es, p2 = e2/es;
            float bm[3], bs[3];
#pragma unroll
            for (int rr = 0; rr < 3; rr++) {
                float mm = -1e30f;
                for (int p = 0; p < 32; p++) mm = fmaxf(mm, rbud[rr*32+p]);
                float sx = 0.f;
                for (int p = 0; p < 32; p++) sx += __expf(rbud[rr*32+p] - mm);
                bm[rr] = mm; bs[rr] = sx;
            }
            float w0s = p0/bs[0], w1s = p1/bs[1], w2s = p2/bs[2];
            float bbv[32], eqs = 0.f, dfs = 0.f;
            for (int p = 0; p < 32; p++) {
                float v = w0s*__expf(rbud[p]-bm[0]) + w1s*__expf(rbud[32+p]-bm[1]) + w2s*__expf(rbud[64+p]-bm[2]);
                bbv[p] = v;
                if (p < 24) eqs += v; else dfs += v;
            }
            bool  mask = vix[b] >= 30.0f;
            float shortfall = 0.4f - dfs;
            float ratio = fminf(shortfall / fmaxf(eqs, 1e-8f), 0.8f);
            bool  apply = mask && (shortfall > 0.f) && (eqs > 1e-8f);
            float bsum = 0.f, bsel[32];
            for (int p = 0; p < 32; p++) {
                float b2 = (p < 24) ? bbv[p]*(1.f-ratio) : bbv[p] + shortfall*(1.f/8.f);
                float v  = apply ? b2 : bbv[p];
                bsel[p] = v; bsum += v;
            }
            float innorm = 1.f / (bsum + 1e-8f);
            for (int p = 0; p < 32; p++)
                out[b*32+p] = mask ? bsel[p]*innorm : bbv[p];
            out[4096 + b*3 + 0] = p0;
            out[4096 + b*3 + 1] = p1;
            out[4096 + b*3 + 2] = p2;
        }
        if (t == 0) {
            grp_wait(bg, 16u * 1026u);
            asm volatile("st.relaxed.gpu.global.u32 [%0], %1;" :: "l"(&g_grp[bg]), "r"(0u) : "memory");
        }
    }
}

extern "C" void kernel_launch(void *const *d_in, const int *in_sizes, int n_in,
                              void *d_out, int out_size)
{
    (void)in_sizes; (void)n_in; (void)out_size;
    static int inited = 0;
    if (!inited) {
        cudaFuncSetAttribute(regime_kernel, cudaFuncAttributeMaxDynamicSharedMemorySize, SMEMB);
        inited = 1;
    }
    regime_kernel<<<NCTA, TPB, SMEMB>>>(
        (const float *)d_in[0],  (const float *)d_in[1],  (const float *)d_in[2],
        (const float *)d_in[3],  (const float *)d_in[4],  (const float *)d_in[5],
        (const float *)d_in[6],  (const float *)d_in[7],  (const float *)d_in[8],
        (const float *)d_in[9],  (const float *)d_in[10], (const float *)d_in[11],
        (const float *)d_in[12], (const float *)d_in[13], (const float *)d_in[14],
        (float *)d_out);
}